// round 11
// baseline (speedup 1.0000x reference)
#include <cuda_runtime.h>
#include <cstdint>
#include <cstring>
#include <vector>
#include <algorithm>

#define B_ROWS 16384
#define D_COLS 2048
#define NCLS   1000

// Scratch (device globals: allocation-free per harness rules)
__device__ unsigned short g_index[B_ROWS];          // permutation, host-computed
__device__ int g_off[NCLS + 1];                     // CSR offsets (by class id)
__device__ unsigned int g_offs[B_ROWS];             // sorted row element-offsets (row*2048)
__device__ unsigned short g_order[1024];            // classes by descending count
__device__ float g_cn[NCLS * D_COLS];               // class_noise matrix (8MB)

// ---------------------------------------------------------------------------
// JAX threefry2x32 (20 rounds), bit-exact. Host+device.
// ---------------------------------------------------------------------------
__host__ __device__ __forceinline__ void threefry2x32(
    uint32_t k0, uint32_t k1, uint32_t x0, uint32_t x1,
    uint32_t &o0, uint32_t &o1)
{
    uint32_t ks0 = k0, ks1 = k1, ks2 = k0 ^ k1 ^ 0x1BD11BDAu;
    x0 += ks0; x1 += ks1;
    const int R[2][4] = {{13, 15, 26, 6}, {17, 29, 16, 24}};
#pragma unroll
    for (int i = 0; i < 5; i++) {
#pragma unroll
        for (int j = 0; j < 4; j++) {
            int r = R[i & 1][j];
            x0 += x1;
            x1 = (x1 << r) | (x1 >> (32 - r));
            x1 ^= x0;
        }
        uint32_t a = (i + 1) % 3 == 0 ? ks0 : ((i + 1) % 3 == 1 ? ks1 : ks2);
        uint32_t b = (i + 2) % 3 == 0 ? ks0 : ((i + 2) % 3 == 1 ? ks1 : ks2);
        x0 += a;
        x1 += b + (uint32_t)(i + 1);
    }
    o0 = x0; o1 = x1;
}

// ---------------------------------------------------------------------------
// XLA f32 ErfInv (Giles polynomial)
// ---------------------------------------------------------------------------
__device__ __forceinline__ float erfinv_f32(float x)
{
    float w = -log1pf(-x * x);
    float p;
    if (w < 5.0f) {
        w -= 2.5f;
        p = 2.81022636e-08f;
        p = fmaf(p, w, 3.43273939e-07f);
        p = fmaf(p, w, -3.5233877e-06f);
        p = fmaf(p, w, -4.39150654e-06f);
        p = fmaf(p, w, 0.00021858087f);
        p = fmaf(p, w, -0.00125372503f);
        p = fmaf(p, w, -0.00417768164f);
        p = fmaf(p, w, 0.246640727f);
        p = fmaf(p, w, 1.50140941f);
    } else {
        w = sqrtf(w) - 3.0f;
        p = -0.000200214257f;
        p = fmaf(p, w, 0.000100950558f);
        p = fmaf(p, w, 0.00134934322f);
        p = fmaf(p, w, -0.00367342844f);
        p = fmaf(p, w, 0.00573950773f);
        p = fmaf(p, w, -0.0076224613f);
        p = fmaf(p, w, 0.00943887047f);
        p = fmaf(p, w, 1.00167406f);
        p = fmaf(p, w, 2.83297682f);
    }
    return p * x;
}

__device__ __forceinline__ float jax_normal(uint32_t nk0, uint32_t nk1, uint32_t idx)
{
    uint32_t b0, b1;
    threefry2x32(nk0, nk1, 0u, idx, b0, b1);
    uint32_t bits = b0 ^ b1;
    float f = __uint_as_float((bits >> 9) | 0x3f800000u);   // [1,2)
    const float lo = -0.99999994039535522461f;               // nextafter(-1,0)
    float u = fmaxf(lo, fmaf(f - 1.0f, 2.0f, lo));
    return 1.41421356237309504880f * erfinv_f32(u);
}

__device__ __forceinline__ float cn_val(float s, float q, float cnt,
                                        uint32_t nk0, uint32_t nk1, uint32_t flat)
{
    float mean = s / cnt;
    float var  = (q - cnt * mean * mean) / (cnt - 1.0f);
    float sd   = sqrtf(fmaxf(var, 0.0f));
    return mean + sd * jax_normal(nk0, nk1, flat);
}

// warp-wide ascending bitonic sort of 32 values
__device__ __forceinline__ unsigned int bitonic32(unsigned int v, int lane)
{
#pragma unroll
    for (int k = 2; k <= 32; k <<= 1) {
#pragma unroll
        for (int j = k >> 1; j > 0; j >>= 1) {
            unsigned int p = __shfl_xor_sync(0xFFFFFFFFu, v, j);
            bool up = ((lane & k) == 0);
            bool keepMin = (((lane & j) == 0) == up);
            v = keepMin ? min(v, p) : max(v, p);
        }
    }
    return v;
}
__device__ __forceinline__ unsigned int bitonic_merge32(unsigned int v, int lane)
{
#pragma unroll
    for (int j = 16; j > 0; j >>= 1) {
        unsigned int p = __shfl_xor_sync(0xFFFFFFFFu, v, j);
        v = ((lane & j) == 0) ? min(v, p) : max(v, p);
    }
    return v;
}

// ---------------------------------------------------------------------------
// Kernel A: CSR build + per-class sort + descending-size class schedule.
// 1024 threads: histogram -> scan -> smem scatter -> per-class warp bitonic
// sort into g_offs -> 1024-wide smem bitonic on (count<<10|class) descending
// producing g_order.
// ---------------------------------------------------------------------------
__global__ __launch_bounds__(1024) void build_csr_kernel(const int* __restrict__ y)
{
    __shared__ int cnt[1024];
    __shared__ int sc[1024];
    __shared__ int cur[1024];
    __shared__ unsigned int keys[1024];
    __shared__ unsigned short rows_sm[B_ROWS];   // 32KB
    int t = threadIdx.x;
    int lane = t & 31;
    int w = t >> 5;
    cnt[t] = 0;
    __syncthreads();
    for (int i = t; i < B_ROWS; i += 1024) atomicAdd(&cnt[y[i]], 1);
    __syncthreads();
    int mycnt = cnt[t];
    sc[t] = mycnt;
    __syncthreads();
    for (int d = 1; d < 1024; d <<= 1) {
        int add = (t >= d) ? sc[t - d] : 0;
        __syncthreads();
        sc[t] += add;
        __syncthreads();
    }
    cur[t] = (t == 0) ? 0 : sc[t - 1];
    if (t <= NCLS) g_off[t] = (t == 0) ? 0 : sc[t - 1];
    // schedule key: descending count, class id tiebreak
    keys[t] = ((unsigned int)mycnt << 10) | (unsigned int)t;
    __syncthreads();
    for (int i = t; i < B_ROWS; i += 1024) {
        int c = y[i];
        int p = atomicAdd(&cur[c], 1);
        rows_sm[p] = (unsigned short)i;
    }
    __syncthreads();
    // warp w sorts classes w, w+32, ... into g_offs
    for (int c = w; c < NCLS; c += 32) {
        int s = (c == 0) ? 0 : sc[c - 1];
        int n = sc[c] - s;
        if (n <= 32) {
            unsigned int v = (lane < n) ? (unsigned int)rows_sm[s + lane] : 0xFFFFFFFFu;
            v = bitonic32(v, lane);
            if (lane < n) g_offs[s + lane] = v * D_COLS;
        } else if (n <= 64) {
            unsigned int v0 = (lane < n) ? (unsigned int)rows_sm[s + lane] : 0xFFFFFFFFu;
            unsigned int v1 = (32 + lane < n) ? (unsigned int)rows_sm[s + 32 + lane] : 0xFFFFFFFFu;
            v0 = bitonic32(v0, lane);
            v1 = bitonic32(v1, lane);
            v1 = __shfl_sync(0xFFFFFFFFu, v1, 31 - lane);
            unsigned int lo = min(v0, v1), hi = max(v0, v1);
            lo = bitonic_merge32(lo, lane);
            hi = bitonic_merge32(hi, lane);
            if (lane < n) g_offs[s + lane] = lo * D_COLS;
            if (32 + lane < n) g_offs[s + 32 + lane] = hi * D_COLS;
        } else if (lane == 0) {                                // never in practice
            for (int a = 0; a < n; a++) {
                int best = a;
                for (int b = a + 1; b < n; b++)
                    if (rows_sm[s + b] < rows_sm[s + best]) best = b;
                unsigned short tv = rows_sm[s + a];
                rows_sm[s + a] = rows_sm[s + best];
                rows_sm[s + best] = tv;
                g_offs[s + a] = (unsigned int)rows_sm[s + a] * D_COLS;
            }
        }
    }
    // 1024-wide smem bitonic, DESCENDING keys -> class schedule
    for (int k = 2; k <= 1024; k <<= 1) {
        for (int j = k >> 1; j > 0; j >>= 1) {
            __syncthreads();
            int ixj = t ^ j;
            if (ixj > t) {
                unsigned int a = keys[t], b = keys[ixj];
                bool desc = ((t & k) == 0);          // descending blocks
                if ((a < b) == desc) { keys[t] = b; keys[ixj] = a; }
            }
        }
    }
    __syncthreads();
    g_order[t] = (unsigned short)(keys[t] & 1023u);
}

// ---------------------------------------------------------------------------
// Kernel B: per-class stats fused with noise generation (R8-proven shape).
// grid (NCLS, 4): one CTA per (scheduled class, 512-float D-chunk); 128 thr.
// Zero prologue: offsets pre-sorted in g_offs; big classes scheduled first.
// ---------------------------------------------------------------------------
__global__ __launch_bounds__(128) void stats_noise_kernel(
    const float* __restrict__ x, uint32_t nk0, uint32_t nk1)
{
    int c = __ldg(&g_order[blockIdx.x]);
    int t = threadIdx.x;
    int beg = __ldg(&g_off[c]);
    int n   = __ldg(&g_off[c + 1]) - beg;
    const unsigned int* ofp = g_offs + beg;

    int col = blockIdx.y * 512 + t * 4;                 // float index in row
    const float* xb = x + col;
    float4 s = {0, 0, 0, 0}, q = {0, 0, 0, 0};

#define ACC(V) \
    s.x += V.x; s.y += V.y; s.z += V.z; s.w += V.w; \
    q.x += V.x*V.x; q.y += V.y*V.y; q.z += V.z*V.z; q.w += V.w*V.w;

    int r = 0;
    for (; r + 4 <= n; r += 4) {
        unsigned int o0 = __ldg(ofp + r);
        unsigned int o1 = __ldg(ofp + r + 1);
        unsigned int o2 = __ldg(ofp + r + 2);
        unsigned int o3 = __ldg(ofp + r + 3);
        float4 v0 = *reinterpret_cast<const float4*>(xb + o0);
        float4 v1 = *reinterpret_cast<const float4*>(xb + o1);
        float4 v2 = *reinterpret_cast<const float4*>(xb + o2);
        float4 v3 = *reinterpret_cast<const float4*>(xb + o3);
        ACC(v0) ACC(v1) ACC(v2) ACC(v3)
    }
    for (; r < n; r++) {
        float4 v = *reinterpret_cast<const float4*>(xb + __ldg(ofp + r));
        ACC(v)
    }
#undef ACC

    float cnt = (float)n;
    uint32_t flat = (uint32_t)c * (uint32_t)D_COLS + (uint32_t)col;
    float4 o;
    o.x = cn_val(s.x, q.x, cnt, nk0, nk1, flat + 0u);
    o.y = cn_val(s.y, q.y, cnt, nk0, nk1, flat + 1u);
    o.z = cn_val(s.z, q.z, cnt, nk0, nk1, flat + 2u);
    o.w = cn_val(s.w, q.w, cnt, nk0, nk1, flat + 3u);
    *reinterpret_cast<float4*>(g_cn + (size_t)c * D_COLS + col) = o;
}

// ---------------------------------------------------------------------------
// Kernel C: out = 0.9*x + 0.1*cn[newY[row]] via packed f32x2 (R7-proven).
// ---------------------------------------------------------------------------
__global__ __launch_bounds__(256) void out_kernel(
    const float* __restrict__ x, const int* __restrict__ y,
    float* __restrict__ out, int out_size)
{
    int row = blockIdx.x;
    int t = threadIdx.x;
    int c = __ldg(&y[g_index[row]]);
    const float4* x4 = reinterpret_cast<const float4*>(x) + (size_t)row * 512;
    const float4* n4 = reinterpret_cast<const float4*>(g_cn) + (size_t)c * 512;
    float4* o4 = reinterpret_cast<float4*>(out) + (size_t)row * 512;

    float4 a0 = __ldcs(x4 + t);
    float4 a1 = __ldcs(x4 + t + 256);
    float4 b0 = __ldg(n4 + t);
    float4 b1 = __ldg(n4 + t + 256);

    const unsigned long long C09 = 0x3f6666663f666666ull;  // {0.9f, 0.9f}
    const unsigned long long C01 = 0x3dcccccd3dcccccdull;  // {0.1f, 0.1f}
#define BLEND(A, O) { \
    ulonglong2 av = *reinterpret_cast<ulonglong2*>(&A); \
    ulonglong2 bv = *reinterpret_cast<ulonglong2*>(&O); \
    unsigned long long r0, r1; \
    asm("mul.rn.f32x2 %0, %1, %2;" : "=l"(r0) : "l"(av.x), "l"(C09)); \
    asm("mul.rn.f32x2 %0, %1, %2;" : "=l"(r1) : "l"(av.y), "l"(C09)); \
    asm("fma.rn.f32x2 %0, %1, %2, %3;" : "=l"(r0) : "l"(bv.x), "l"(C01), "l"(r0)); \
    asm("fma.rn.f32x2 %0, %1, %2, %3;" : "=l"(r1) : "l"(bv.y), "l"(C01), "l"(r1)); \
    av.x = r0; av.y = r1; \
    A = *reinterpret_cast<float4*>(&av); }

    BLEND(a0, b0)
    BLEND(a1, b1)
#undef BLEND
    __stcs(o4 + t, a0);
    __stcs(o4 + t + 256, a1);

    if (t == 0) {
        long long p = (long long)B_ROWS * D_COLS + row;
        if (p < (long long)out_size) out[p] = (float)c;   // newY as numeric value
    }
}

// ---------------------------------------------------------------------------
// Permutation upload via kernel parameters (no memcpy nodes).
// ---------------------------------------------------------------------------
struct IdxChunk { unsigned short v[8192]; };

__global__ void upload_idx_kernel(IdxChunk ch, int off)
{
    int t = blockIdx.x * blockDim.x + threadIdx.x;
    if (t < 8192) g_index[off + t] = ch.v[t];
}

// ---------------------------------------------------------------------------
// Host: jax.random key derivation + permutation (2 stable-sort rounds).
// ---------------------------------------------------------------------------
extern "C" void kernel_launch(void* const* d_in, const int* in_sizes, int n_in,
                              void* d_out, int out_size)
{
    const float* x = (const float*)d_in[0];
    const int*   y = (const int*)d_in[1];
    float* out = (float*)d_out;

    uint32_t nk0, nk1, pk0, pk1;
    threefry2x32(0u, 42u, 0u, 0u, nk0, nk1);
    threefry2x32(0u, 42u, 0u, 1u, pk0, pk1);

    std::vector<uint16_t> perm(B_ROWS), tmp(B_ROWS);
    std::vector<uint64_t> buf(B_ROWS);
    for (int i = 0; i < B_ROWS; i++) perm[i] = (uint16_t)i;
    uint32_t k0 = pk0, k1 = pk1;
    const int NUM_ROUNDS = 2;   // ceil(3*log(16384)/log(2^32-1))
    for (int r = 0; r < NUM_ROUNDS; r++) {
        uint32_t t0, t1, s0, s1;
        threefry2x32(k0, k1, 0u, 0u, t0, t1);
        threefry2x32(k0, k1, 0u, 1u, s0, s1);
        k0 = t0; k1 = t1;
        for (int i = 0; i < B_ROWS; i++) {
            uint32_t b0, b1;
            threefry2x32(s0, s1, 0u, (uint32_t)i, b0, b1);
            buf[i] = ((uint64_t)(b0 ^ b1) << 32) | (uint32_t)i;
        }
        std::sort(buf.begin(), buf.end());
        for (int j = 0; j < B_ROWS; j++)
            tmp[j] = perm[(uint32_t)(buf[j] & 0xFFFFFFFFu)];
        perm.swap(tmp);
    }

    IdxChunk c0, c1;
    memcpy(c0.v, perm.data(),        8192 * sizeof(uint16_t));
    memcpy(c1.v, perm.data() + 8192, 8192 * sizeof(uint16_t));
    upload_idx_kernel<<<32, 256>>>(c0, 0);
    upload_idx_kernel<<<32, 256>>>(c1, 8192);

    build_csr_kernel<<<1, 1024>>>(y);
    dim3 sgrid(NCLS, 4);
    stats_noise_kernel<<<sgrid, 128>>>(x, nk0, nk1);
    out_kernel<<<B_ROWS, 256>>>(x, y, out, out_size);
}

// round 13
// speedup vs baseline: 1.2649x; 1.2649x over previous
#include <cuda_runtime.h>
#include <cstdint>
#include <cstring>
#include <vector>
#include <algorithm>

#define B_ROWS 16384
#define D_COLS 2048
#define NCLS   1000

// Scratch (device globals: allocation-free per harness rules)
__device__ unsigned short g_index[B_ROWS];          // permutation, host-computed
__device__ unsigned short g_rows[B_ROWS];           // row ids grouped by class (unsorted)
__device__ int g_off[NCLS + 1];                     // CSR offsets
__device__ unsigned int g_offs[B_ROWS + 16];        // sorted row element-offsets (+pad)
__device__ float g_cn[NCLS * D_COLS];               // class_noise matrix (8MB)

// ---------------------------------------------------------------------------
// JAX threefry2x32 (20 rounds), bit-exact. Host+device.
// ---------------------------------------------------------------------------
__host__ __device__ __forceinline__ void threefry2x32(
    uint32_t k0, uint32_t k1, uint32_t x0, uint32_t x1,
    uint32_t &o0, uint32_t &o1)
{
    uint32_t ks0 = k0, ks1 = k1, ks2 = k0 ^ k1 ^ 0x1BD11BDAu;
    x0 += ks0; x1 += ks1;
    const int R[2][4] = {{13, 15, 26, 6}, {17, 29, 16, 24}};
#pragma unroll
    for (int i = 0; i < 5; i++) {
#pragma unroll
        for (int j = 0; j < 4; j++) {
            int r = R[i & 1][j];
            x0 += x1;
            x1 = (x1 << r) | (x1 >> (32 - r));
            x1 ^= x0;
        }
        uint32_t a = (i + 1) % 3 == 0 ? ks0 : ((i + 1) % 3 == 1 ? ks1 : ks2);
        uint32_t b = (i + 2) % 3 == 0 ? ks0 : ((i + 2) % 3 == 1 ? ks1 : ks2);
        x0 += a;
        x1 += b + (uint32_t)(i + 1);
    }
    o0 = x0; o1 = x1;
}

// ---------------------------------------------------------------------------
// XLA f32 ErfInv (Giles polynomial)
// ---------------------------------------------------------------------------
__device__ __forceinline__ float erfinv_f32(float x)
{
    float w = -log1pf(-x * x);
    float p;
    if (w < 5.0f) {
        w -= 2.5f;
        p = 2.81022636e-08f;
        p = fmaf(p, w, 3.43273939e-07f);
        p = fmaf(p, w, -3.5233877e-06f);
        p = fmaf(p, w, -4.39150654e-06f);
        p = fmaf(p, w, 0.00021858087f);
        p = fmaf(p, w, -0.00125372503f);
        p = fmaf(p, w, -0.00417768164f);
        p = fmaf(p, w, 0.246640727f);
        p = fmaf(p, w, 1.50140941f);
    } else {
        w = sqrtf(w) - 3.0f;
        p = -0.000200214257f;
        p = fmaf(p, w, 0.000100950558f);
        p = fmaf(p, w, 0.00134934322f);
        p = fmaf(p, w, -0.00367342844f);
        p = fmaf(p, w, 0.00573950773f);
        p = fmaf(p, w, -0.0076224613f);
        p = fmaf(p, w, 0.00943887047f);
        p = fmaf(p, w, 1.00167406f);
        p = fmaf(p, w, 2.83297682f);
    }
    return p * x;
}

__device__ __forceinline__ float jax_normal(uint32_t nk0, uint32_t nk1, uint32_t idx)
{
    uint32_t b0, b1;
    threefry2x32(nk0, nk1, 0u, idx, b0, b1);
    uint32_t bits = b0 ^ b1;
    float f = __uint_as_float((bits >> 9) | 0x3f800000u);   // [1,2)
    const float lo = -0.99999994039535522461f;               // nextafter(-1,0)
    float u = fmaxf(lo, fmaf(f - 1.0f, 2.0f, lo));
    return 1.41421356237309504880f * erfinv_f32(u);
}

__device__ __forceinline__ float cn_val(float s, float q, float cnt,
                                        uint32_t nk0, uint32_t nk1, uint32_t flat)
{
    float mean = s / cnt;
    float var  = (q - cnt * mean * mean) / (cnt - 1.0f);
    float sd   = sqrtf(fmaxf(var, 0.0f));
    return mean + sd * jax_normal(nk0, nk1, flat);
}

// warp-wide ascending bitonic sort of 32 values
__device__ __forceinline__ unsigned int bitonic32(unsigned int v, int lane)
{
#pragma unroll
    for (int k = 2; k <= 32; k <<= 1) {
#pragma unroll
        for (int j = k >> 1; j > 0; j >>= 1) {
            unsigned int p = __shfl_xor_sync(0xFFFFFFFFu, v, j);
            bool up = ((lane & k) == 0);
            bool keepMin = (((lane & j) == 0) == up);
            v = keepMin ? min(v, p) : max(v, p);
        }
    }
    return v;
}
__device__ __forceinline__ unsigned int bitonic_merge32(unsigned int v, int lane)
{
#pragma unroll
    for (int j = 16; j > 0; j >>= 1) {
        unsigned int p = __shfl_xor_sync(0xFFFFFFFFu, v, j);
        v = ((lane & j) == 0) ? min(v, p) : max(v, p);
    }
    return v;
}

// ---------------------------------------------------------------------------
// Kernel A: CSR build (R8-proven). Single CTA, 1024 threads:
// histogram -> scan -> smem scatter -> coalesced g_rows write-out.
// ---------------------------------------------------------------------------
__global__ __launch_bounds__(1024) void build_csr_kernel(const int* __restrict__ y)
{
    __shared__ int cnt[1024];
    __shared__ int sc[1024];
    __shared__ int cur[1024];
    __shared__ unsigned short rows_sm[B_ROWS];   // 32KB
    int t = threadIdx.x;
    cnt[t] = 0;
    __syncthreads();
    for (int i = t; i < B_ROWS; i += 1024) atomicAdd(&cnt[y[i]], 1);
    __syncthreads();
    sc[t] = cnt[t];
    __syncthreads();
    for (int d = 1; d < 1024; d <<= 1) {
        int add = (t >= d) ? sc[t - d] : 0;
        __syncthreads();
        sc[t] += add;
        __syncthreads();
    }
    cur[t] = (t == 0) ? 0 : sc[t - 1];
    if (t <= NCLS) g_off[t] = (t == 0) ? 0 : sc[t - 1];
    __syncthreads();
    for (int i = t; i < B_ROWS; i += 1024) {
        int c = y[i];
        int p = atomicAdd(&cur[c], 1);
        rows_sm[p] = (unsigned short)i;
    }
    __syncthreads();
    uint4* dst = reinterpret_cast<uint4*>(g_rows);
    const uint4* src = reinterpret_cast<const uint4*>(rows_sm);
    for (int i = t; i < B_ROWS / 8; i += 1024) dst[i] = src[i];
}

// ---------------------------------------------------------------------------
// Kernel A2: per-class sort, ONE WARP PER CLASS (1000 parallel CTAs) —
// the 26cyc SHFL latency is hidden across CTAs, unlike the serial-in-one-CTA
// R10/R11 version. Writes presorted element offsets to g_offs.
// ---------------------------------------------------------------------------
__global__ __launch_bounds__(32) void sort_rows_kernel()
{
    int c = blockIdx.x;
    int lane = threadIdx.x;
    int s = __ldg(&g_off[c]);
    int n = __ldg(&g_off[c + 1]) - s;
    if (n <= 32) {
        unsigned int v = (lane < n) ? (unsigned int)g_rows[s + lane] : 0xFFFFFFFFu;
        v = bitonic32(v, lane);
        if (lane < n) g_offs[s + lane] = v * D_COLS;
    } else if (n <= 64) {
        unsigned int v0 = (lane < n) ? (unsigned int)g_rows[s + lane] : 0xFFFFFFFFu;
        unsigned int v1 = (32 + lane < n) ? (unsigned int)g_rows[s + 32 + lane] : 0xFFFFFFFFu;
        v0 = bitonic32(v0, lane);
        v1 = bitonic32(v1, lane);
        v1 = __shfl_sync(0xFFFFFFFFu, v1, 31 - lane);
        unsigned int lo = min(v0, v1), hi = max(v0, v1);
        lo = bitonic_merge32(lo, lane);
        hi = bitonic_merge32(hi, lane);
        if (lane < n) g_offs[s + lane] = lo * D_COLS;
        if (32 + lane < n) g_offs[s + 32 + lane] = hi * D_COLS;
    } else if (lane == 0) {                    // never in practice
        for (int a = 0; a < n; a++) {
            unsigned int best = 0xFFFFFFFFu;
            for (int b = 0; b < n; b++) {
                unsigned int rv = g_rows[s + b];
                bool used = false;
                for (int u = 0; u < a; u++)
                    if (g_offs[s + u] == rv * D_COLS) { used = true; break; }
                if (!used && rv < best) best = rv;
            }
            g_offs[s + a] = best * D_COLS;
        }
    }
}

// ---------------------------------------------------------------------------
// Kernel B: per-class stats fused with noise generation, cp.async pipeline.
// grid (NCLS, 4): one CTA per (class, 512-float D-chunk); 128 thr.
// Each thread fire-and-forgets up to 16 independent 16B LDGSTS per batch
// (MLP=16, zero register pressure), reads back ONLY its own bytes (no
// barriers), accumulates rows in ascending order (deterministic).
// ---------------------------------------------------------------------------
__global__ __launch_bounds__(128) void stats_noise_kernel(
    const float* __restrict__ x, uint32_t nk0, uint32_t nk1)
{
    __shared__ __align__(16) float buf[16 * 512];   // 32KB
    int c = blockIdx.x;
    int t = threadIdx.x;
    int beg = __ldg(&g_off[c]);
    int n   = __ldg(&g_off[c + 1]) - beg;
    const unsigned int* ofp = g_offs + beg;

    int col = blockIdx.y * 512 + t * 4;             // float index in row
    const float* xb = x + col;
    float* myslot = buf + t * 4;                    // this thread's 16B per row
    uint32_t smem_base = (uint32_t)__cvta_generic_to_shared(myslot);

    float4 s = {0, 0, 0, 0}, q = {0, 0, 0, 0};

    for (int b0 = 0; b0 < n; b0 += 16) {
        int bn = min(16, n - b0);
        unsigned int off[16];
#pragma unroll
        for (int i = 0; i < 16; i++)                // 16 independent loads, one latency
            off[i] = __ldg(ofp + b0 + i);           // g_offs padded: safe past end
#pragma unroll
        for (int r = 0; r < 16; r++) {
            if (r < bn) {
                const float* src = xb + off[r];
                asm volatile("cp.async.cg.shared.global [%0], [%1], 16;"
                             :: "r"(smem_base + (unsigned)r * 2048u), "l"(src) : "memory");
            }
        }
        asm volatile("cp.async.commit_group;" ::: "memory");
        asm volatile("cp.async.wait_group 0;" ::: "memory");
        for (int r = 0; r < bn; r++) {
            float4 v = *reinterpret_cast<const float4*>(myslot + r * 512);
            s.x += v.x; s.y += v.y; s.z += v.z; s.w += v.w;
            q.x += v.x*v.x; q.y += v.y*v.y; q.z += v.z*v.z; q.w += v.w*v.w;
        }
    }

    float cnt = (float)n;
    uint32_t flat = (uint32_t)c * (uint32_t)D_COLS + (uint32_t)col;
    float4 o;
    o.x = cn_val(s.x, q.x, cnt, nk0, nk1, flat + 0u);
    o.y = cn_val(s.y, q.y, cnt, nk0, nk1, flat + 1u);
    o.z = cn_val(s.z, q.z, cnt, nk0, nk1, flat + 2u);
    o.w = cn_val(s.w, q.w, cnt, nk0, nk1, flat + 3u);
    *reinterpret_cast<float4*>(g_cn + (size_t)c * D_COLS + col) = o;
}

// ---------------------------------------------------------------------------
// Kernel C: out = 0.9*x + 0.1*cn[newY[row]] via packed f32x2 (R7-proven).
// ---------------------------------------------------------------------------
__global__ __launch_bounds__(256) void out_kernel(
    const float* __restrict__ x, const int* __restrict__ y,
    float* __restrict__ out, int out_size)
{
    int row = blockIdx.x;
    int t = threadIdx.x;
    int c = __ldg(&y[g_index[row]]);
    const float4* x4 = reinterpret_cast<const float4*>(x) + (size_t)row * 512;
    const float4* n4 = reinterpret_cast<const float4*>(g_cn) + (size_t)c * 512;
    float4* o4 = reinterpret_cast<float4*>(out) + (size_t)row * 512;

    float4 a0 = __ldcs(x4 + t);
    float4 a1 = __ldcs(x4 + t + 256);
    float4 b0 = __ldg(n4 + t);
    float4 b1 = __ldg(n4 + t + 256);

    const unsigned long long C09 = 0x3f6666663f666666ull;  // {0.9f, 0.9f}
    const unsigned long long C01 = 0x3dcccccd3dcccccdull;  // {0.1f, 0.1f}
#define BLEND(A, O) { \
    ulonglong2 av = *reinterpret_cast<ulonglong2*>(&A); \
    ulonglong2 bv = *reinterpret_cast<ulonglong2*>(&O); \
    unsigned long long r0, r1; \
    asm("mul.rn.f32x2 %0, %1, %2;" : "=l"(r0) : "l"(av.x), "l"(C09)); \
    asm("mul.rn.f32x2 %0, %1, %2;" : "=l"(r1) : "l"(av.y), "l"(C09)); \
    asm("fma.rn.f32x2 %0, %1, %2, %3;" : "=l"(r0) : "l"(bv.x), "l"(C01), "l"(r0)); \
    asm("fma.rn.f32x2 %0, %1, %2, %3;" : "=l"(r1) : "l"(bv.y), "l"(C01), "l"(r1)); \
    av.x = r0; av.y = r1; \
    A = *reinterpret_cast<float4*>(&av); }

    BLEND(a0, b0)
    BLEND(a1, b1)
#undef BLEND
    __stcs(o4 + t, a0);
    __stcs(o4 + t + 256, a1);

    if (t == 0) {
        long long p = (long long)B_ROWS * D_COLS + row;
        if (p < (long long)out_size) out[p] = (float)c;   // newY as numeric value
    }
}

// ---------------------------------------------------------------------------
// Permutation upload via kernel parameters (no memcpy nodes).
// ---------------------------------------------------------------------------
struct IdxChunk { unsigned short v[8192]; };

__global__ void upload_idx_kernel(IdxChunk ch, int off)
{
    int t = blockIdx.x * blockDim.x + threadIdx.x;
    if (t < 8192) g_index[off + t] = ch.v[t];
}

// ---------------------------------------------------------------------------
// Host: jax.random key derivation + permutation (2 stable-sort rounds).
// ---------------------------------------------------------------------------
extern "C" void kernel_launch(void* const* d_in, const int* in_sizes, int n_in,
                              void* d_out, int out_size)
{
    const float* x = (const float*)d_in[0];
    const int*   y = (const int*)d_in[1];
    float* out = (float*)d_out;

    uint32_t nk0, nk1, pk0, pk1;
    threefry2x32(0u, 42u, 0u, 0u, nk0, nk1);
    threefry2x32(0u, 42u, 0u, 1u, pk0, pk1);

    std::vector<uint16_t> perm(B_ROWS), tmp(B_ROWS);
    std::vector<uint64_t> buf(B_ROWS);
    for (int i = 0; i < B_ROWS; i++) perm[i] = (uint16_t)i;
    uint32_t k0 = pk0, k1 = pk1;
    const int NUM_ROUNDS = 2;   // ceil(3*log(16384)/log(2^32-1))
    for (int r = 0; r < NUM_ROUNDS; r++) {
        uint32_t t0, t1, s0, s1;
        threefry2x32(k0, k1, 0u, 0u, t0, t1);
        threefry2x32(k0, k1, 0u, 1u, s0, s1);
        k0 = t0; k1 = t1;
        for (int i = 0; i < B_ROWS; i++) {
            uint32_t b0, b1;
            threefry2x32(s0, s1, 0u, (uint32_t)i, b0, b1);
            buf[i] = ((uint64_t)(b0 ^ b1) << 32) | (uint32_t)i;
        }
        std::sort(buf.begin(), buf.end());
        for (int j = 0; j < B_ROWS; j++)
            tmp[j] = perm[(uint32_t)(buf[j] & 0xFFFFFFFFu)];
        perm.swap(tmp);
    }

    IdxChunk c0, c1;
    memcpy(c0.v, perm.data(),        8192 * sizeof(uint16_t));
    memcpy(c1.v, perm.data() + 8192, 8192 * sizeof(uint16_t));
    upload_idx_kernel<<<32, 256>>>(c0, 0);
    upload_idx_kernel<<<32, 256>>>(c1, 8192);

    build_csr_kernel<<<1, 1024>>>(y);
    sort_rows_kernel<<<NCLS, 32>>>();
    dim3 sgrid(NCLS, 4);
    stats_noise_kernel<<<sgrid, 128>>>(x, nk0, nk1);
    out_kernel<<<B_ROWS, 256>>>(x, y, out, out_size);
}